// round 10
// baseline (speedup 1.0000x reference)
#include <cuda_runtime.h>
#include <cuda_bf16.h>
#include <math.h>
#include <stdint.h>

// Problem constants
#define B_  32
#define N_  4096
#define C_  512
#define EPS_INV 10.0f          // 1/EPS_SINKHORN

#define CHUNKS 16              // chunk-blocks per batch -> grid 512
#define ROWS_PER_BLOCK (N_ / CHUNKS)   // 256
#define THREADS1 256           // 8 warps
#define NWARPS (THREADS1 / 32)

#define TILE_ROWS 8            // one row per warp per tile
#define STAGES 3               // smem ring: 3 x 16KB = 48KB dynamic EXACTLY
#define NTILES (ROWS_PER_BLOCK / TILE_ROWS)     // 32
#define TILE_F4 (TILE_ROWS * C_ / 4)            // 1024 float4 per tile

// Scratch (allocation-free rule: __device__ globals)
__device__ float        g_vec[B_ * CHUNKS * C_];   // partial weighted sums: 1 MB
__device__ float        g_E[B_ * CHUNKS];          // partial exp-sums
__device__ unsigned int g_cnt[B_];                 // zero-init; last block resets -> replayable

__device__ __forceinline__ void cp_async16(float4* smem_dst, const float4* gmem_src) {
    uint32_t s = (uint32_t)__cvta_generic_to_shared(smem_dst);
    asm volatile("cp.async.cg.shared.global [%0], [%1], 16;\n" :: "r"(s), "l"(gmem_src));
}
#define CP_COMMIT()  asm volatile("cp.async.commit_group;\n" ::: "memory")
#define CP_WAIT(n)   asm volatile("cp.async.wait_group %0;\n" :: "n"(n) : "memory")

// ---------------------------------------------------------------------------
// Fused single-pass kernel with a cp.async smem ring. ZERO static __shared__:
// the 48KB dynamic ring is the only smem (static+dynamic must fit 48KB
// without opt-in attributes — the cause of rounds 8/9 launch failures).
// Epilogue scratch (sacc, sEw, s_Etot, s_last) aliases the dead tile ring.
// Prompt lives in 16 registers per lane. Bulk GMEM->SMEM cp.async keeps ~2
// tiles (32KB) per block in flight with zero register cost. Last chunk-block
// per batch performs the cross-chunk combine.
//
// Per row: e = exp(10*(cos_sim - 1)) (shift m=0 valid since cos_sim <= 1),
// accumulate (e/|v|)*v and e. Softmax Z folds out analytically:
//   obs = num / (E + 1e-6*S),  total_mass = E / S,  S = E + exp(-10*dustbin).
// ---------------------------------------------------------------------------
__global__ __launch_bounds__(THREADS1, 4)
void uot_fused(const float* __restrict__ prompt,
               const float* __restrict__ vfeats,
               const float* __restrict__ dustbin_param,
               float* __restrict__ out)
{
    extern __shared__ float4 s_tiles[];      // STAGES * TILE_F4 float4 = 48KB

    const int b     = blockIdx.x / CHUNKS;
    const int chunk = blockIdx.x % CHUNKS;
    const int tid   = threadIdx.x;
    const int wid   = tid >> 5;
    const int lane  = tid & 31;

    // Epilogue aliases into the (then-dead) tile ring — no static smem at all
    float* sacc   = (float*)s_tiles;         // NWARPS*C_ floats = 16KB
    float* sEw    = sacc + NWARPS * C_;      // NWARPS floats
    float* sEtot  = sEw + NWARPS;            // 1 float
    int*   sLast  = (int*)(sEtot + 1);       // 1 int

    const float* base = vfeats + ((size_t)b * N_ + (size_t)chunk * ROWS_PER_BLOCK) * C_;
    const float4* gbase = (const float4*)base;

    // ---- Prologue: fill the ring (tiles 0..STAGES-1) ----
    #pragma unroll
    for (int s = 0; s < STAGES; s++) {
        float4* dst = s_tiles + s * TILE_F4;
        const float4* src = gbase + s * TILE_F4;
        #pragma unroll
        for (int k = 0; k < 4; k++)
            cp_async16(dst + tid + k * THREADS1, src + tid + k * THREADS1);
        CP_COMMIT();
    }

    // ---- Prompt into registers + its norm (per-warp; overlaps prologue) ----
    float4 p[4];
    {
        const float4* pr = (const float4*)(prompt + (size_t)b * C_);
        float ss = 0.f;
        #pragma unroll
        for (int j = 0; j < 4; j++) {
            p[j] = __ldg(pr + j * 32 + lane);
            ss += p[j].x * p[j].x + p[j].y * p[j].y + p[j].z * p[j].z + p[j].w * p[j].w;
        }
        #pragma unroll
        for (int o = 16; o; o >>= 1) ss += __shfl_xor_sync(0xffffffffu, ss, o);
        float pinv = rsqrtf(fmaxf(ss, 1e-24f));
        // Pre-scale prompt by 1/|p| so the inner loop needs no extra multiply
        #pragma unroll
        for (int j = 0; j < 4; j++) {
            p[j].x *= pinv; p[j].y *= pinv; p[j].z *= pinv; p[j].w *= pinv;
        }
    }

    // ---- Main loop over tiles ----
    float acc[16];
    #pragma unroll
    for (int i = 0; i < 16; i++) acc[i] = 0.f;
    float Eacc = 0.f;

    for (int t = 0; t < NTILES; t++) {
        CP_WAIT(STAGES - 1);                 // tile t landed (<=2 groups pending)
        __syncthreads();

        // Process: warp wid owns row wid of this tile
        const float4* rowp = s_tiles + (t % STAGES) * TILE_F4 + wid * (C_ / 4);
        float4 v[4];
        float dpv = 0.f, dvv = 0.f;
        #pragma unroll
        for (int j = 0; j < 4; j++) v[j] = rowp[j * 32 + lane];
        #pragma unroll
        for (int j = 0; j < 4; j++) {
            dpv += v[j].x * p[j].x + v[j].y * p[j].y + v[j].z * p[j].z + v[j].w * p[j].w;
            dvv += v[j].x * v[j].x + v[j].y * v[j].y + v[j].z * v[j].z + v[j].w * v[j].w;
        }
        #pragma unroll
        for (int o = 16; o; o >>= 1) {
            dpv += __shfl_xor_sync(0xffffffffu, dpv, o);
            dvv += __shfl_xor_sync(0xffffffffu, dvv, o);
        }
        float invn = rsqrtf(fmaxf(dvv, 1e-24f));
        float e    = __expf(EPS_INV * (dpv * invn - 1.0f));   // p already unit-norm
        float w    = e * invn;               // weight applied to the RAW row
        Eacc += e;
        #pragma unroll
        for (int j = 0; j < 4; j++) {
            acc[j * 4 + 0] += w * v[j].x;
            acc[j * 4 + 1] += w * v[j].y;
            acc[j * 4 + 2] += w * v[j].z;
            acc[j * 4 + 3] += w * v[j].w;
        }

        __syncthreads();                     // all reads of buf (t%STAGES) done

        // Refill buf with tile t+STAGES (empty commit keeps group count aligned)
        const int tn = t + STAGES;
        if (tn < NTILES) {
            float4* dst = s_tiles + (tn % STAGES) * TILE_F4;
            const float4* src = gbase + (size_t)tn * TILE_F4;
            #pragma unroll
            for (int k = 0; k < 4; k++)
                cp_async16(dst + tid + k * THREADS1, src + tid + k * THREADS1);
        }
        CP_COMMIT();
    }

    // ---- Cross-warp combine: reuse the (now free) tile ring ----
    float4* sa4 = (float4*)(sacc + wid * C_);
    #pragma unroll
    for (int j = 0; j < 4; j++)
        sa4[j * 32 + lane] = make_float4(acc[j*4+0], acc[j*4+1], acc[j*4+2], acc[j*4+3]);
    if (lane == 0) sEw[wid] = Eacc;
    __syncthreads();

    const int slot = b * CHUNKS + chunk;
    #pragma unroll
    for (int c = tid; c < C_; c += THREADS1) {
        float s = 0.f;
        #pragma unroll
        for (int w = 0; w < NWARPS; w++) s += sacc[w * C_ + c];
        g_vec[slot * C_ + c] = s;
    }
    if (tid == 0) {
        float s = 0.f;
        #pragma unroll
        for (int w = 0; w < NWARPS; w++) s += sEw[w];
        g_E[slot] = s;
    }

    // ---- Last-block-per-batch does the final combine ----
    __syncthreads();
    if (tid == 0) {
        __threadfence();                     // release partials
        unsigned int old = atomicAdd(&g_cnt[b], 1u);
        *sLast = (old == CHUNKS - 1);
    }
    __syncthreads();
    if (!*sLast) return;
    __threadfence();                         // acquire others' partials

    if (tid < CHUNKS) {                      // CHUNKS == 16
        float e = g_E[b * CHUNKS + tid];
        #pragma unroll
        for (int o = CHUNKS / 2; o; o >>= 1)
            e += __shfl_xor_sync(0x0000ffffu, e, o);
        if (tid == 0) *sEtot = e;
    }
    __syncthreads();

    const float E    = *sEtot;
    const float ebin = __expf(-EPS_INV * dustbin_param[0]);
    const float S    = E + ebin;
    const float dinv = 1.0f / (E + 1e-6f * S);

    #pragma unroll
    for (int c = tid; c < C_; c += THREADS1) {
        float num = 0.f;
        #pragma unroll
        for (int ch = 0; ch < CHUNKS; ch++)
            num += g_vec[(b * CHUNKS + ch) * C_ + c];
        out[b * C_ + c] = num * dinv;
    }
    if (tid == 0) {
        out[B_ * C_ + b] = E / S;            // total_mass
        g_cnt[b] = 0;                        // reset for next graph replay
    }
}

// ---------------------------------------------------------------------------
extern "C" void kernel_launch(void* const* d_in, const int* in_sizes, int n_in,
                              void* d_out, int out_size)
{
    const float* prompt  = (const float*)d_in[0];   // (32,1,512)
    const float* vfeats  = (const float*)d_in[1];   // (32,4096,512)
    // d_in[2] = dustbin_token : unused by the reference computation
    const float* dparam  = (const float*)d_in[3];   // (1,)
    float* out = (float*)d_out;

    const int smem = STAGES * TILE_F4 * sizeof(float4);   // 49152B dynamic, 0 static
    uot_fused<<<B_ * CHUNKS, THREADS1, smem>>>(prompt, vfeats, dparam, out);
}